// round 2
// baseline (speedup 1.0000x reference)
#include <cuda_runtime.h>
#include <math.h>

#define N_NODES   100000
#define N_FEAT    128
#define N_CLASSES 40
#define N_EDGES   1600000
#define K_HOPS    2
#define CHUNKS    (N_CLASSES / 4)   // 10 float4 per row

#define SCAN_BLK  1024
#define SCAN_NB   ((N_NODES + SCAN_BLK - 1) / SCAN_BLK)   // 98

// ---- scratch (__device__ globals; no allocation allowed) ----
__device__ float g_bufA[N_NODES * N_CLASSES];   // 16 MB
__device__ float g_bufB[N_NODES * N_CLASSES];   // 16 MB
__device__ int   g_deg[N_NODES];
__device__ float g_dis[N_NODES];
__device__ int   g_incl[N_NODES];               // per-block inclusive scan
__device__ int   g_bsum[SCAN_NB];
__device__ int   g_boff[SCAN_NB];
__device__ int   g_rowstart[N_NODES + 1];
__device__ int   g_cursor[N_NODES];
__device__ int2  g_csr[N_EDGES];                // {src, bits(w)} 12.8 MB

// ---------------------------------------------------------------------------
__global__ void k_zero_deg() {
    int i = blockIdx.x * blockDim.x + threadIdx.x;
    if (i < N_NODES) g_deg[i] = 0;
}

__global__ void k_hist(const int* __restrict__ dst, int E) {
    int e = blockIdx.x * blockDim.x + threadIdx.x;
    if (e < E) atomicAdd(&g_deg[dst[e]], 1);
}

// ---- scan stage 1: per-block inclusive scan of deg -----------------------
__global__ void k_scan1() {
    __shared__ int s[SCAN_BLK];
    int gid = blockIdx.x * SCAN_BLK + threadIdx.x;
    int v = (gid < N_NODES) ? g_deg[gid] : 0;
    s[threadIdx.x] = v;
    __syncthreads();
    // Hillis-Steele
    for (int off = 1; off < SCAN_BLK; off <<= 1) {
        int t = (threadIdx.x >= off) ? s[threadIdx.x - off] : 0;
        __syncthreads();
        s[threadIdx.x] += t;
        __syncthreads();
    }
    if (gid < N_NODES) g_incl[gid] = s[threadIdx.x];
    if (threadIdx.x == SCAN_BLK - 1) g_bsum[blockIdx.x] = s[threadIdx.x];
}

// ---- scan stage 2: serial scan of 98 block sums --------------------------
__global__ void k_scan2(int E) {
    if (threadIdx.x == 0) {
        int run = 0;
        for (int b = 0; b < SCAN_NB; b++) {
            g_boff[b] = run;
            run += g_bsum[b];
        }
        g_rowstart[N_NODES] = E;
    }
}

// ---- scan stage 3: exclusive rowstart + cursor + dis ---------------------
__global__ void k_scan3() {
    int i = blockIdx.x * blockDim.x + threadIdx.x;
    if (i >= N_NODES) return;
    int d = g_deg[i];
    int ex = g_incl[i] - d + g_boff[i / SCAN_BLK];
    g_rowstart[i] = ex;
    g_cursor[i]   = ex;
    g_dis[i] = rsqrtf((float)d + 1.0f);   // +1 = self loop
}

// ---- CSR fill: csr[p] = {src, dis[src]*dis[dst]} -------------------------
__global__ void k_fill(const int* __restrict__ src, const int* __restrict__ dst, int E) {
    int e = blockIdx.x * blockDim.x + threadIdx.x;
    if (e >= E) return;
    int s = src[e];
    int d = dst[e];
    float w = g_dis[s] * g_dis[d];
    int p = atomicAdd(&g_cursor[d], 1);
    g_csr[p] = make_int2(s, __float_as_int(w));
}

// ---- y0 = x @ W  (thread per node, W in shared) ---------------------------
__global__ void k_gemm(const float* __restrict__ x, const float* __restrict__ W) {
    __shared__ float Ws[N_FEAT * N_CLASSES];  // 20 KB
    for (int i = threadIdx.x; i < N_FEAT * N_CLASSES; i += blockDim.x)
        Ws[i] = W[i];
    __syncthreads();

    int node = blockIdx.x * blockDim.x + threadIdx.x;
    if (node >= N_NODES) return;

    float acc[N_CLASSES];
#pragma unroll
    for (int c = 0; c < N_CLASSES; c++) acc[c] = 0.0f;

    const float4* xr = (const float4*)(x + (size_t)node * N_FEAT);
#pragma unroll 1
    for (int k0 = 0; k0 < N_FEAT; k0 += 4) {
        float4 xv = __ldg(&xr[k0 >> 2]);
#pragma unroll
        for (int c = 0; c < N_CLASSES; c++) {
            acc[c] += xv.x * Ws[(k0 + 0) * N_CLASSES + c]
                    + xv.y * Ws[(k0 + 1) * N_CLASSES + c]
                    + xv.z * Ws[(k0 + 2) * N_CLASSES + c]
                    + xv.w * Ws[(k0 + 3) * N_CLASSES + c];
        }
    }
    float* out = g_bufA + (size_t)node * N_CLASSES;
#pragma unroll
    for (int c = 0; c < N_CLASSES; c++) out[c] = acc[c];
}

// ---- hop: gather. out[d] = sum_e w_e * in[src_e] + dis[d]^2 * in[d] ------
__global__ __launch_bounds__(128) void k_hop(int aToB) {
    int node = blockIdx.x * blockDim.x + threadIdx.x;
    if (node >= N_NODES) return;

    const float* in  = aToB ? g_bufA : g_bufB;
    float*       out = aToB ? g_bufB : g_bufA;

    int beg = g_rowstart[node];
    int end = g_rowstart[node + 1];

    float4 acc[CHUNKS];
#pragma unroll
    for (int c = 0; c < CHUNKS; c++) acc[c] = make_float4(0.f, 0.f, 0.f, 0.f);

    for (int j = beg; j < end; j++) {
        int2 ew = __ldg(&g_csr[j]);
        float w = __int_as_float(ew.y);
        const float4* r = (const float4*)(in + (size_t)ew.x * N_CLASSES);
#pragma unroll
        for (int c = 0; c < CHUNKS; c++) {
            float4 v = __ldg(&r[c]);
            acc[c].x += w * v.x;
            acc[c].y += w * v.y;
            acc[c].z += w * v.z;
            acc[c].w += w * v.w;
        }
    }

    float di = g_dis[node];
    float si = di * di;
    const float4* rs = (const float4*)(in + (size_t)node * N_CLASSES);
    float4* os = (float4*)(out + (size_t)node * N_CLASSES);
#pragma unroll
    for (int c = 0; c < CHUNKS; c++) {
        float4 v = __ldg(&rs[c]);
        float4 o;
        o.x = acc[c].x + si * v.x;
        o.y = acc[c].y + si * v.y;
        o.z = acc[c].z + si * v.z;
        o.w = acc[c].w + si * v.w;
        os[c] = o;
    }
}

// ---- epilogue: logits = y + b; out = log_softmax(logits) ------------------
__global__ void k_final(const float* __restrict__ b, float* __restrict__ out, int finalInA) {
    int i = blockIdx.x * blockDim.x + threadIdx.x;
    if (i >= N_NODES) return;
    const float* y = (finalInA ? g_bufA : g_bufB) + (size_t)i * N_CLASSES;

    float l[N_CLASSES];
    float m = -INFINITY;
#pragma unroll
    for (int c = 0; c < N_CLASSES; c++) {
        l[c] = y[c] + b[c];
        m = fmaxf(m, l[c]);
    }
    float sum = 0.0f;
#pragma unroll
    for (int c = 0; c < N_CLASSES; c++) sum += expf(l[c] - m);
    float lse = m + logf(sum);

    float* o = out + (size_t)i * N_CLASSES;
#pragma unroll
    for (int c = 0; c < N_CLASSES; c++) o[c] = l[c] - lse;
}

// ---------------------------------------------------------------------------
extern "C" void kernel_launch(void* const* d_in, const int* in_sizes, int n_in,
                              void* d_out, int out_size) {
    const float* x  = (const float*)d_in[0];
    const float* W  = (const float*)d_in[1];
    const float* b  = (const float*)d_in[2];
    const int*   ei = (const int*)d_in[3];
    // d_in[4] is K (scalar, = 2); fixed as K_HOPS.

    const int E = in_sizes[3] / 2;
    const int* src = ei;
    const int* dst = ei + E;

    const int T = 256;

    // ---- CSR build (once; reused by both hops) ----
    k_zero_deg<<<(N_NODES + T - 1) / T, T>>>();
    k_hist<<<(E + T - 1) / T, T>>>(dst, E);
    k_scan1<<<SCAN_NB, SCAN_BLK>>>();
    k_scan2<<<1, 32>>>(E);
    k_scan3<<<(N_NODES + T - 1) / T, T>>>();
    k_fill<<<(E + T - 1) / T, T>>>(src, dst, E);

    // ---- project first: y0 = x @ W -> bufA ----
    k_gemm<<<(N_NODES + T - 1) / T, T>>>(x, W);

    // ---- K hops of propagation in 40-dim space (ping-pong A<->B) ----
    int aToB = 1;
    for (int h = 0; h < K_HOPS; h++) {
        k_hop<<<(N_NODES + 127) / 128, 128>>>(aToB);
        aToB ^= 1;
    }
    // after even K, result is back in bufA (aToB==1 => final in A)
    k_final<<<(N_NODES + T - 1) / T, T>>>(b, (float*)d_out, aToB);
}

// round 3
// speedup vs baseline: 1.3182x; 1.3182x over previous
#include <cuda_runtime.h>
#include <math.h>

#define N_NODES   100000
#define N_FEAT    128
#define N_CLASSES 40
#define N_EDGES   1600000
#define K_HOPS    2

#define SCAN_BLK  1024
#define SCAN_NB   ((N_NODES + SCAN_BLK - 1) / SCAN_BLK)   // 98

// ---- scratch (__device__ globals; no allocation allowed) ----
__device__ float g_bufA[N_NODES * N_CLASSES];   // 16 MB
__device__ float g_bufB[N_NODES * N_CLASSES];   // 16 MB
__device__ int   g_deg[N_NODES];
__device__ float g_dis[N_NODES];
__device__ int   g_incl[N_NODES];
__device__ int   g_bsum[SCAN_NB];
__device__ int   g_boff[SCAN_NB];
__device__ int   g_rowstart[N_NODES + 1];
__device__ int   g_cursor[N_NODES];
__device__ int2  g_csr[N_EDGES];                // {src, bits(w)} 12.8 MB

// ---------------------------------------------------------------------------
__global__ void k_zero_deg() {
    int i = blockIdx.x * blockDim.x + threadIdx.x;
    if (i < N_NODES) g_deg[i] = 0;
}

__global__ void k_hist(const int* __restrict__ dst, int E) {
    int e = blockIdx.x * blockDim.x + threadIdx.x;
    if (e < E) atomicAdd(&g_deg[dst[e]], 1);
}

// ---- scan stage 1: per-block inclusive scan of deg -----------------------
__global__ void k_scan1() {
    __shared__ int s[SCAN_BLK];
    int gid = blockIdx.x * SCAN_BLK + threadIdx.x;
    int v = (gid < N_NODES) ? g_deg[gid] : 0;
    s[threadIdx.x] = v;
    __syncthreads();
    for (int off = 1; off < SCAN_BLK; off <<= 1) {
        int t = (threadIdx.x >= off) ? s[threadIdx.x - off] : 0;
        __syncthreads();
        s[threadIdx.x] += t;
        __syncthreads();
    }
    if (gid < N_NODES) g_incl[gid] = s[threadIdx.x];
    if (threadIdx.x == SCAN_BLK - 1) g_bsum[blockIdx.x] = s[threadIdx.x];
}

// ---- scan stage 2: parallel scan of 98 block sums (one block) ------------
__global__ void k_scan2(int E) {
    __shared__ int s[128];
    int v = (threadIdx.x < SCAN_NB) ? g_bsum[threadIdx.x] : 0;
    s[threadIdx.x] = v;
    __syncthreads();
    for (int off = 1; off < 128; off <<= 1) {
        int t = (threadIdx.x >= off) ? s[threadIdx.x - off] : 0;
        __syncthreads();
        s[threadIdx.x] += t;
        __syncthreads();
    }
    if (threadIdx.x < SCAN_NB) g_boff[threadIdx.x] = s[threadIdx.x] - v;  // exclusive
    if (threadIdx.x == 0) g_rowstart[N_NODES] = E;
}

// ---- scan stage 3: exclusive rowstart + cursor + dis ---------------------
__global__ void k_scan3() {
    int i = blockIdx.x * blockDim.x + threadIdx.x;
    if (i >= N_NODES) return;
    int d = g_deg[i];
    int ex = g_incl[i] - d + g_boff[i / SCAN_BLK];
    g_rowstart[i] = ex;
    g_cursor[i]   = ex;
    g_dis[i] = rsqrtf((float)d + 1.0f);   // +1 = self loop
}

// ---- CSR fill: csr[p] = {src, dis[src]*dis[dst]} -------------------------
__global__ void k_fill(const int* __restrict__ src, const int* __restrict__ dst, int E) {
    int e = blockIdx.x * blockDim.x + threadIdx.x;
    if (e >= E) return;
    int s = src[e];
    int d = dst[e];
    float w = g_dis[s] * g_dis[d];
    int p = atomicAdd(&g_cursor[d], 1);
    g_csr[p] = make_int2(s, __float_as_int(w));
}

// ---- y0 = x @ W : 2 nodes per thread, W transposed in shared -------------
__global__ __launch_bounds__(128) void k_gemm(const float* __restrict__ x,
                                              const float* __restrict__ W) {
    __shared__ float Wt[N_CLASSES * N_FEAT];  // 20 KB, [c][k] layout
    for (int i = threadIdx.x; i < N_FEAT * N_CLASSES; i += blockDim.x) {
        int k = i / N_CLASSES, c = i % N_CLASSES;
        Wt[c * N_FEAT + k] = W[i];
    }
    __syncthreads();

    const int HALF = N_NODES / 2;  // 50000
    int t = blockIdx.x * blockDim.x + threadIdx.x;
    if (t >= HALF) return;
    int n0 = t, n1 = t + HALF;

    float acc0[N_CLASSES], acc1[N_CLASSES];
#pragma unroll
    for (int c = 0; c < N_CLASSES; c++) { acc0[c] = 0.f; acc1[c] = 0.f; }

    const float4* xr0 = (const float4*)(x + (size_t)n0 * N_FEAT);
    const float4* xr1 = (const float4*)(x + (size_t)n1 * N_FEAT);

#pragma unroll 1
    for (int k0 = 0; k0 < N_FEAT; k0 += 4) {
        float4 a = __ldg(&xr0[k0 >> 2]);
        float4 b = __ldg(&xr1[k0 >> 2]);
#pragma unroll
        for (int c = 0; c < N_CLASSES; c++) {
            float4 w = *(const float4*)&Wt[c * N_FEAT + k0];
            acc0[c] += a.x * w.x + a.y * w.y + a.z * w.z + a.w * w.w;
            acc1[c] += b.x * w.x + b.y * w.y + b.z * w.z + b.w * w.w;
        }
    }
    float* o0 = g_bufA + (size_t)n0 * N_CLASSES;
    float* o1 = g_bufA + (size_t)n1 * N_CLASSES;
#pragma unroll
    for (int c = 0; c < N_CLASSES; c++) { o0[c] = acc0[c]; o1[c] = acc1[c]; }
}

// ---- warp-per-node gather core --------------------------------------------
// Row = 40 floats. acc0 = f[lane], acc1 = f[32+lane] (lanes 0-7 only).
__device__ __forceinline__ void gather_node(const float* __restrict__ in, int node,
                                            int lane, float& acc0, float& acc1) {
    int beg = g_rowstart[node];
    int end = g_rowstart[node + 1];
    acc0 = 0.f; acc1 = 0.f;

    int j = beg;
    for (; j + 2 <= end; j += 2) {
        int2 e0 = __ldg(&g_csr[j]);
        int2 e1 = __ldg(&g_csr[j + 1]);
        float w0 = __int_as_float(e0.y);
        float w1 = __int_as_float(e1.y);
        const float* r0 = in + (size_t)e0.x * N_CLASSES;
        const float* r1 = in + (size_t)e1.x * N_CLASSES;
        float v0 = __ldg(r0 + lane);
        float v1 = __ldg(r1 + lane);
        acc0 += w0 * v0 + w1 * v1;
        if (lane < 8) {
            acc1 += w0 * __ldg(r0 + 32 + lane) + w1 * __ldg(r1 + 32 + lane);
        }
    }
    if (j < end) {
        int2 e0 = __ldg(&g_csr[j]);
        float w0 = __int_as_float(e0.y);
        const float* r0 = in + (size_t)e0.x * N_CLASSES;
        acc0 += w0 * __ldg(r0 + lane);
        if (lane < 8) acc1 += w0 * __ldg(r0 + 32 + lane);
    }
    // self-loop term
    float di = g_dis[node];
    float si = di * di;
    const float* rs = in + (size_t)node * N_CLASSES;
    acc0 += si * __ldg(rs + lane);
    if (lane < 8) acc1 += si * __ldg(rs + 32 + lane);
}

// ---- hop 1: bufA -> bufB --------------------------------------------------
__global__ __launch_bounds__(256) void k_hop1() {
    int node = (blockIdx.x * blockDim.x + threadIdx.x) >> 5;
    int lane = threadIdx.x & 31;
    if (node >= N_NODES) return;
    float acc0, acc1;
    gather_node(g_bufA, node, lane, acc0, acc1);
    float* o = g_bufB + (size_t)node * N_CLASSES;
    o[lane] = acc0;
    if (lane < 8) o[32 + lane] = acc1;
}

// ---- hop 2 fused with bias + log_softmax: bufB -> d_out -------------------
__global__ __launch_bounds__(256) void k_hop2(const float* __restrict__ b,
                                              float* __restrict__ out) {
    int node = (blockIdx.x * blockDim.x + threadIdx.x) >> 5;
    int lane = threadIdx.x & 31;
    if (node >= N_NODES) return;
    float acc0, acc1;
    gather_node(g_bufB, node, lane, acc0, acc1);

    float l0 = acc0 + __ldg(b + lane);
    float l1 = (lane < 8) ? (acc1 + __ldg(b + 32 + lane)) : -INFINITY;

    // warp max over all 40 logits
    float m = fmaxf(l0, l1);
#pragma unroll
    for (int off = 16; off > 0; off >>= 1)
        m = fmaxf(m, __shfl_xor_sync(0xFFFFFFFFu, m, off));

    float e = expf(l0 - m) + ((lane < 8) ? expf(l1 - m) : 0.f);
#pragma unroll
    for (int off = 16; off > 0; off >>= 1)
        e += __shfl_xor_sync(0xFFFFFFFFu, e, off);

    float lse = m + logf(e);
    float* o = out + (size_t)node * N_CLASSES;
    o[lane] = l0 - lse;
    if (lane < 8) o[32 + lane] = l1 - lse;
}

// ---------------------------------------------------------------------------
extern "C" void kernel_launch(void* const* d_in, const int* in_sizes, int n_in,
                              void* d_out, int out_size) {
    const float* x  = (const float*)d_in[0];
    const float* W  = (const float*)d_in[1];
    const float* b  = (const float*)d_in[2];
    const int*   ei = (const int*)d_in[3];
    // d_in[4] is K (scalar, = 2); fixed as K_HOPS.

    const int E = in_sizes[3] / 2;
    const int* src = ei;
    const int* dst = ei + E;

    const int T = 256;

    // ---- CSR build (once; reused by both hops) ----
    k_zero_deg<<<(N_NODES + T - 1) / T, T>>>();
    k_hist<<<(E + T - 1) / T, T>>>(dst, E);
    k_scan1<<<SCAN_NB, SCAN_BLK>>>();
    k_scan2<<<1, 128>>>(E);
    k_scan3<<<(N_NODES + T - 1) / T, T>>>();
    k_fill<<<(E + T - 1) / T, T>>>(src, dst, E);

    // ---- project first: y0 = x @ W -> bufA ----
    k_gemm<<<(N_NODES / 2 + 127) / 128, 128>>>(x, W);

    // ---- 2 hops, warp per node; hop2 fused with softmax ----
    const int WARPS_PER_BLK = 8;  // 256 threads
    int hop_blocks = (N_NODES + WARPS_PER_BLK - 1) / WARPS_PER_BLK;
    k_hop1<<<hop_blocks, 256>>>();
    k_hop2<<<hop_blocks, 256>>>(b, (float*)d_out);
}